// round 8
// baseline (speedup 1.0000x reference)
#include <cuda_runtime.h>
#include <cuda_fp16.h>
#include <math.h>

// x = (4, 64, 128, 128) fp32, K=7 -> out (4, 49, 16384) fp32
#define BATCH   4
#define CHN     64
#define HT      128
#define WD      128
#define HW      (HT * WD)            // 16384
#define KW      7
#define PADR    3
#define TILEH   32
#define TILEW   16
#define TRH     (TILEH + 2 * PADR)   // 38
#define TRW     (TILEW + 2 * PADR)   // 22
#define NPIX    (TRH * TRW)          // 836
#define NTHREADS 512                 // one center per thread, 16 warps/SM
#define NOFF    (KW * KW)            // 49
#define EPAD    56                   // 112B/thread: 7 granules (odd) -> conflict-free
#define EPSV    1e-7f

// smem: fp16 tile [NPIX][64] swizzled | fp32 rnorms [NPIX] | fp16 exps [NTHREADS][EPAD]
#define TILE_HALVES  (NPIX * 64)
#define TILE_BYTES_S (TILE_HALVES * 2)               // 107,008
#define NORM_BYTES   (NPIX * 4)                      // 3,344
#define EXPS_BYTES   (NTHREADS * EPAD * 2)           // 57,344
#define SMEM_BYTES   (TILE_BYTES_S + NORM_BYTES + EXPS_BYTES)  // 167,696 B

__global__ __launch_bounds__(NTHREADS, 1)
void region_sim_kernel(const float* __restrict__ x, float* __restrict__ out) {
    extern __shared__ __align__(16) char smem_raw[];
    __half* tile   = (__half*)smem_raw;                               // [NPIX][64]
    float*  rnorms = (float*)(smem_raw + TILE_BYTES_S);               // [NPIX] (1/||v||)
    __half* exps   = (__half*)(smem_raw + TILE_BYTES_S + NORM_BYTES); // [NTHREADS][EPAD]

    const int b   = blockIdx.z;
    const int w0  = blockIdx.x * TILEW;
    const int h0  = blockIdx.y * TILEH;
    const int tid = threadIdx.x;

    // ---- Phase 1: gmem fp32 -> fp16 smem tile; q fully unrolled for LDG MLP ----
    const float* xb = x + (size_t)b * CHN * HW;
#pragma unroll 1
    for (int p = tid; p < NPIX; p += NTHREADS) {
        int r   = p / TRW;
        int col = p - r * TRW;
        int gh  = h0 - PADR + r;
        int gw  = w0 - PADR + col;
        const bool inb = (gh >= 0 && gh < HT && gw >= 0 && gw < WD);
        const int gi = gh * WD + gw;
        __half2* tp = (__half2*)(tile + p * 64);
        const int sw = p & 7;
#pragma unroll
        for (int q = 0; q < 8; q++) {
            __half2 h0v = __float2half2_rn(0.f), h1v = h0v, h2v = h0v, h3v = h0v;
            if (inb) {
                const float* x0 = xb + (size_t)(q * 8) * HW + gi;
                h0v = __floats2half2_rn(x0[0],      x0[HW]);
                h1v = __floats2half2_rn(x0[2 * HW], x0[3 * HW]);
                h2v = __floats2half2_rn(x0[4 * HW], x0[5 * HW]);
                h3v = __floats2half2_rn(x0[6 * HW], x0[7 * HW]);
            }
            __half2* dst = tp + (size_t)(q ^ sw) * 4;
            dst[0] = h0v; dst[1] = h1v; dst[2] = h2v; dst[3] = h3v;
        }
    }
    __syncthreads();

    // ---- Phase 2: reciprocal fp32 norms from the fp16 values ----
#pragma unroll 1
    for (int p = tid; p < NPIX; p += NTHREADS) {
        const uint4* tp = (const uint4*)(tile + p * 64);
        const int sw = p & 7;
        float4 s = make_float4(0.f, 0.f, 0.f, 0.f);
#pragma unroll
        for (int q = 0; q < 8; q++) {
            uint4 hv = tp[q ^ sw];
            float2 f0 = __half22float2(*(__half2*)&hv.x);
            float2 f1 = __half22float2(*(__half2*)&hv.y);
            float2 f2 = __half22float2(*(__half2*)&hv.z);
            float2 f3 = __half22float2(*(__half2*)&hv.w);
            s.x += f0.x * f0.x + f2.x * f2.x;
            s.y += f0.y * f0.y + f2.y * f2.y;
            s.z += f1.x * f1.x + f3.x * f3.x;
            s.w += f1.y * f1.y + f3.y * f3.y;
        }
        float ss = (s.x + s.y) + (s.z + s.w);
        // zero (padded) pixels: dot==0 exactly -> sim=0 -> exp=1, matches reference
        rnorms[p] = rsqrtf(ss + 1e-12f);
    }
    __syncthreads();

    // ---- Phase 3: per o-row, interleave 7 neighbors across q-steps (SW pipeline) ----
    const int lw = tid & (TILEW - 1);
    const int lh = tid >> 4;
    const int colC = PADR + lw;
    const int rC   = PADR + lh;
    const int pC   = rC * TRW + colC;

    __half2 cen[32];
    {
        const uint4* cp = (const uint4*)(tile + pC * 64);
        const int sw = pC & 7;
#pragma unroll
        for (int q = 0; q < 8; q++) {
            uint4 hv = cp[q ^ sw];
            cen[4 * q + 0] = *(__half2*)&hv.x;
            cen[4 * q + 1] = *(__half2*)&hv.y;
            cen[4 * q + 2] = *(__half2*)&hv.z;
            cen[4 * q + 3] = *(__half2*)&hv.w;
        }
    }
    const float rnC = rnorms[pC];
    __half* my_exps = exps + tid * EPAD;

    float den = 0.f;
    const __half2 hz = __float2half2_rn(0.f);

#pragma unroll 1
    for (int o = -PADR; o <= PADR; o++) {
        const int pb = (rC + o) * TRW + (colC - PADR);   // leftmost neighbor of this row
        const __half* rowp = tile + pb * 64;
        const int swb = pb & 7;

        int swj[7];
        float rnj[7];
#pragma unroll
        for (int j = 0; j < 7; j++) {
            swj[j] = (swb + j) & 7;
            rnj[j] = rnorms[pb + j];
        }

        __half2 acc[7][4];
#pragma unroll
        for (int j = 0; j < 7; j++) {
            acc[j][0] = hz; acc[j][1] = hz; acc[j][2] = hz; acc[j][3] = hz;
        }

        // q-major: 7 independent LDS.128 per step, then 28 HFMA2 — loads of step
        // q+1 overlap the FMA burst of step q.
#pragma unroll
        for (int q = 0; q < 8; q++) {
#pragma unroll
            for (int j = 0; j < 7; j++) {
                uint4 hv = *(const uint4*)(rowp + j * 64 + ((q ^ swj[j]) << 3));
                acc[j][0] = __hfma2(cen[4 * q + 0], *(__half2*)&hv.x, acc[j][0]);
                acc[j][1] = __hfma2(cen[4 * q + 1], *(__half2*)&hv.y, acc[j][1]);
                acc[j][2] = __hfma2(cen[4 * q + 2], *(__half2*)&hv.z, acc[j][2]);
                acc[j][3] = __hfma2(cen[4 * q + 3], *(__half2*)&hv.w, acc[j][3]);
            }
        }

        const int kk0 = (o + PADR) * KW;
#pragma unroll
        for (int j = 0; j < 7; j++) {
            float2 f0 = __half22float2(acc[j][0]);
            float2 f1 = __half22float2(acc[j][1]);
            float2 f2 = __half22float2(acc[j][2]);
            float2 f3 = __half22float2(acc[j][3]);
            float dot = ((f0.x + f0.y) + (f1.x + f1.y))
                      + ((f2.x + f2.y) + (f3.x + f3.y));
            float e = __expf(dot * (rnC * rnj[j]));   // sim in [-1,1]
            den += e;
            my_exps[kk0 + j] = __float2half_rn(e);
        }
    }

    // ---- Phase 4: normalize from smem, coalesced stores ----
    const float ri = __fdividef(1.f, den);
    const size_t obase = (size_t)b * NOFF * HW + (size_t)(h0 + lh) * WD + (w0 + lw);
#pragma unroll 1
    for (int g = 0; g < 6; g++) {                  // 6 x 8 = 48
        uint4 hv = *(const uint4*)(my_exps + g * 8);
        float2 f0 = __half22float2(*(__half2*)&hv.x);
        float2 f1 = __half22float2(*(__half2*)&hv.y);
        float2 f2 = __half22float2(*(__half2*)&hv.z);
        float2 f3 = __half22float2(*(__half2*)&hv.w);
        const size_t ob = obase + (size_t)(g * 8) * HW;
        out[ob]          = f0.x * ri;
        out[ob + HW]     = f0.y * ri;
        out[ob + 2 * HW] = f1.x * ri;
        out[ob + 3 * HW] = f1.y * ri;
        out[ob + 4 * HW] = f2.x * ri;
        out[ob + 5 * HW] = f2.y * ri;
        out[ob + 6 * HW] = f3.x * ri;
        out[ob + 7 * HW] = f3.y * ri;
    }
    out[obase + (size_t)48 * HW] = __half2float(my_exps[48]) * ri;   // tail kk=48
}

extern "C" void kernel_launch(void* const* d_in, const int* in_sizes, int n_in,
                              void* d_out, int out_size) {
    (void)in_sizes; (void)n_in; (void)out_size;
    const float* x = (const float*)d_in[0];
    float* out = (float*)d_out;

    cudaFuncSetAttribute(region_sim_kernel,
                         cudaFuncAttributeMaxDynamicSharedMemorySize, SMEM_BYTES);

    dim3 grid(WD / TILEW, HT / TILEH, BATCH);   // 8 x 4 x 4 = 128 blocks = 1 wave
    region_sim_kernel<<<grid, NTHREADS, SMEM_BYTES>>>(x, out);
}

// round 9
// speedup vs baseline: 1.1875x; 1.1875x over previous
#include <cuda_runtime.h>
#include <cuda_fp16.h>
#include <math.h>

// x = (4, 64, 128, 128) fp32, K=7 -> out (4, 49, 16384) fp32
#define BATCH   4
#define CHN     64
#define HT      128
#define WD      128
#define HW      (HT * WD)            // 16384
#define KW      7
#define PADR    3
#define TILEH   32
#define TILEW   16
#define TRH     (TILEH + 2 * PADR)   // 38
#define TRW     (TILEW + 2 * PADR)   // 22
#define NPIX    (TRH * TRW)          // 836
#define NTHREADS 512                 // 16 warps; warp w owns center rows 2w,2w+1
#define NOFF    (KW * KW)            // 49
#define EPAD    56                   // 112B/thread: 7 granules (odd) -> conflict-free
#define EPSV    1e-7f

// smem: fp16 tile [NPIX][64] SW-swizzled | fp32 rnorms [NPIX] | fp16 exps [512][EPAD]
#define TILE_HALVES  (NPIX * 64)
#define TILE_BYTES_S (TILE_HALVES * 2)               // 107,008
#define NORM_BYTES   (NPIX * 4)                      // 3,344
#define EXPS_BYTES   (NTHREADS * EPAD * 2)           // 57,344
#define SMEM_BYTES   (TILE_BYTES_S + NORM_BYTES + EXPS_BYTES)  // 167,696 B

__device__ __forceinline__ void ldsm_x4(unsigned& r0, unsigned& r1,
                                        unsigned& r2, unsigned& r3, unsigned addr) {
    asm volatile("ldmatrix.sync.aligned.m8n8.x4.shared.b16 {%0,%1,%2,%3},[%4];"
                 : "=r"(r0), "=r"(r1), "=r"(r2), "=r"(r3) : "r"(addr));
}
__device__ __forceinline__ void ldsm_x2(unsigned& r0, unsigned& r1, unsigned addr) {
    asm volatile("ldmatrix.sync.aligned.m8n8.x2.shared.b16 {%0,%1},[%2];"
                 : "=r"(r0), "=r"(r1) : "r"(addr));
}
__device__ __forceinline__ void mma16816(float& d0, float& d1, float& d2, float& d3,
                                         unsigned a0, unsigned a1, unsigned a2, unsigned a3,
                                         unsigned b0, unsigned b1) {
    asm volatile("mma.sync.aligned.m16n8k16.row.col.f32.f16.f16.f32 "
                 "{%0,%1,%2,%3},{%4,%5,%6,%7},{%8,%9},{%0,%1,%2,%3};"
                 : "+f"(d0), "+f"(d1), "+f"(d2), "+f"(d3)
                 : "r"(a0), "r"(a1), "r"(a2), "r"(a3), "r"(b0), "r"(b1));
}

__global__ __launch_bounds__(NTHREADS, 1)
void region_sim_kernel(const float* __restrict__ x, float* __restrict__ out) {
    extern __shared__ __align__(16) char smem_raw[];
    __half* tile   = (__half*)smem_raw;                               // [NPIX][64]
    float*  rnorms = (float*)(smem_raw + TILE_BYTES_S);               // [NPIX]
    __half* exps   = (__half*)(smem_raw + TILE_BYTES_S + NORM_BYTES); // [512][EPAD]

    const int b   = blockIdx.z;
    const int w0  = blockIdx.x * TILEW;
    const int h0  = blockIdx.y * TILEH;
    const int tid = threadIdx.x;

    // ---- Phase 1: gmem fp32 -> fp16 smem tile (16B chunk XOR swizzle == SW128) ----
    const float* xb = x + (size_t)b * CHN * HW;
#pragma unroll 1
    for (int p = tid; p < NPIX; p += NTHREADS) {
        int r   = p / TRW;
        int col = p - r * TRW;
        int gh  = h0 - PADR + r;
        int gw  = w0 - PADR + col;
        const bool inb = (gh >= 0 && gh < HT && gw >= 0 && gw < WD);
        const int gi = gh * WD + gw;
        __half2* tp = (__half2*)(tile + p * 64);
        const int sw = p & 7;
#pragma unroll
        for (int q = 0; q < 8; q++) {
            __half2 h0v = __float2half2_rn(0.f), h1v = h0v, h2v = h0v, h3v = h0v;
            if (inb) {
                const float* x0 = xb + (size_t)(q * 8) * HW + gi;
                h0v = __floats2half2_rn(x0[0],      x0[HW]);
                h1v = __floats2half2_rn(x0[2 * HW], x0[3 * HW]);
                h2v = __floats2half2_rn(x0[4 * HW], x0[5 * HW]);
                h3v = __floats2half2_rn(x0[6 * HW], x0[7 * HW]);
            }
            __half2* dst = tp + (size_t)(q ^ sw) * 4;
            dst[0] = h0v; dst[1] = h1v; dst[2] = h2v; dst[3] = h3v;
        }
    }
    __syncthreads();

    // ---- Phase 2: reciprocal fp32 norms from the fp16 values ----
#pragma unroll 1
    for (int p = tid; p < NPIX; p += NTHREADS) {
        const uint4* tp = (const uint4*)(tile + p * 64);
        const int sw = p & 7;
        float4 s = make_float4(0.f, 0.f, 0.f, 0.f);
#pragma unroll
        for (int q = 0; q < 8; q++) {
            uint4 hv = tp[q ^ sw];
            float2 f0 = __half22float2(*(__half2*)&hv.x);
            float2 f1 = __half22float2(*(__half2*)&hv.y);
            float2 f2 = __half22float2(*(__half2*)&hv.z);
            float2 f3 = __half22float2(*(__half2*)&hv.w);
            s.x += f0.x * f0.x + f2.x * f2.x;
            s.y += f0.y * f0.y + f2.y * f2.y;
            s.z += f1.x * f1.x + f3.x * f3.x;
            s.w += f1.y * f1.y + f3.y * f3.y;
        }
        float ss = (s.x + s.y) + (s.z + s.w);
        rnorms[p] = rsqrtf(ss + 1e-12f);   // padded zeros: dot==0 -> sim=0 -> e=1 (ref match)
    }
    __syncthreads();

    // ---- Phase 3: Gram-band via mma.sync; warp w -> center rows 2w, 2w+1 ----
    const int w    = tid >> 5;
    const int lane = tid & 31;
    const unsigned tile_b = (unsigned)__cvta_generic_to_shared(tile);

    // ldmatrix lane decomposition
    const int a_row = (lane & 7) + (((lane >> 3) & 1) << 3);  // 0..15
    const int a_sel = lane >> 4;                              // k-chunk within step
    const int b_n   = lane & 7;
    const int b_sel = (lane >> 3) & 1;                        // lanes>=16 duplicate 0..15

#pragma unroll 1
    for (int half = 0; half < 2; half++) {
        const int hrow = 2 * w + half;          // center row 0..31
        const int rCt  = PADR + hrow;
        const int pa0  = rCt * TRW + PADR;      // first center pixel of the row
        const int cbase = hrow * 16;            // center index base (== phase-4 tid)

        // A fragments: 16 centers x 64ch, 4 k-steps
        unsigned Af[4][4];
        {
            const int pixA = pa0 + a_row;
            const unsigned baseA = tile_b + pixA * 128;
            const int swA = pixA & 7;
#pragma unroll
            for (int ks = 0; ks < 4; ks++)
                ldsm_x4(Af[ks][0], Af[ks][1], Af[ks][2], Af[ks][3],
                        baseA + (((2 * ks + a_sel) ^ swA) << 4));
        }

#pragma unroll 1
        for (int o = 0; o < 7; o++) {
            const int pb = (rCt - 3 + o) * TRW;   // neighbor row, col 0
#pragma unroll
            for (int nt = 0; nt < 3; nt++) {
                const int pixB = pb + nt * 8 + b_n;
                const unsigned baseB = tile_b + pixB * 128;
                const int swB = pixB & 7;
                float d0 = 0.f, d1 = 0.f, d2 = 0.f, d3 = 0.f;
#pragma unroll
                for (int ks = 0; ks < 4; ks++) {
                    unsigned bf0, bf1;
                    ldsm_x2(bf0, bf1, baseB + (((2 * ks + b_sel) ^ swB) << 4));
                    mma16816(d0, d1, d2, d3,
                             Af[ks][0], Af[ks][1], Af[ks][2], Af[ks][3], bf0, bf1);
                }
                // D frag -> band elements: exps[center][o*7 + (n-m)] = fp16(exp(sim))
                const int mlo = lane >> 2;
                const int nc  = nt * 8 + ((lane & 3) << 1);
                const float dd[4] = {d0, d1, d2, d3};
#pragma unroll
                for (int e4 = 0; e4 < 4; e4++) {
                    const int m = mlo + ((e4 >> 1) << 3);   // +8 for d2,d3
                    const int n = nc + (e4 & 1);
                    const unsigned kc = (unsigned)(n - m);
                    if (kc <= 6u) {
                        float sim = dd[e4] * (rnorms[pa0 + m] * rnorms[pb + n]);
                        float e = __expf(sim);              // sim in [-1,1]
                        exps[(cbase + m) * EPAD + o * 7 + kc] = __float2half_rn(e);
                    }
                }
            }
        }
    }
    __syncwarp();   // warp w wrote exactly centers 32w..32w+31 == its own threads

    // ---- Phase 4: per-thread softmax normalize + coalesced stores ----
    const __half* my_exps = exps + tid * EPAD;
    float den = 0.f;
#pragma unroll
    for (int g = 0; g < 6; g++) {
        uint4 hv = *(const uint4*)(my_exps + g * 8);
        float2 f0 = __half22float2(*(__half2*)&hv.x);
        float2 f1 = __half22float2(*(__half2*)&hv.y);
        float2 f2 = __half22float2(*(__half2*)&hv.z);
        float2 f3 = __half22float2(*(__half2*)&hv.w);
        den += ((f0.x + f0.y) + (f1.x + f1.y)) + ((f2.x + f2.y) + (f3.x + f3.y));
    }
    den += __half2float(my_exps[48]);
    const float ri = __fdividef(1.f, den);

    const int lw = tid & (TILEW - 1);
    const int lh = tid >> 4;
    const size_t obase = (size_t)b * NOFF * HW + (size_t)(h0 + lh) * WD + (w0 + lw);
#pragma unroll 1
    for (int g = 0; g < 6; g++) {
        uint4 hv = *(const uint4*)(my_exps + g * 8);
        float2 f0 = __half22float2(*(__half2*)&hv.x);
        float2 f1 = __half22float2(*(__half2*)&hv.y);
        float2 f2 = __half22float2(*(__half2*)&hv.z);
        float2 f3 = __half22float2(*(__half2*)&hv.w);
        const size_t ob = obase + (size_t)(g * 8) * HW;
        out[ob]          = f0.x * ri;
        out[ob + HW]     = f0.y * ri;
        out[ob + 2 * HW] = f1.x * ri;
        out[ob + 3 * HW] = f1.y * ri;
        out[ob + 4 * HW] = f2.x * ri;
        out[ob + 5 * HW] = f2.y * ri;
        out[ob + 6 * HW] = f3.x * ri;
        out[ob + 7 * HW] = f3.y * ri;
    }
    out[obase + (size_t)48 * HW] = __half2float(my_exps[48]) * ri;
}

extern "C" void kernel_launch(void* const* d_in, const int* in_sizes, int n_in,
                              void* d_out, int out_size) {
    (void)in_sizes; (void)n_in; (void)out_size;
    const float* x = (const float*)d_in[0];
    float* out = (float*)d_out;

    cudaFuncSetAttribute(region_sim_kernel,
                         cudaFuncAttributeMaxDynamicSharedMemorySize, SMEM_BYTES);

    dim3 grid(WD / TILEW, HT / TILEH, BATCH);   // 8 x 4 x 4 = 128 blocks = 1 wave
    region_sim_kernel<<<grid, NTHREADS, SMEM_BYTES>>>(x, out);
}